// round 3
// baseline (speedup 1.0000x reference)
#include <cuda_runtime.h>
#include <cstdint>

#define NROWS 262144
#define DDIM 64
#define KCB 512
#define GRID 152
#define CTA_THREADS 512
#define PAIRS_PER_CTA 8           // 16 warps -> 8 warp-pairs
#define ROWS_PER_BATCH 8
#define NBATCH (NROWS / ROWS_PER_BATCH)   // 32768
#define XS_STRIDE 66              // u64 per staged row (64 + 2 pad: kills STS bank conflicts)

typedef unsigned long long u64;

// device scratch (no allocations allowed)
__device__ float g_embT[KCB * DDIM];            // codebook transposed [K][D] for gather
__device__ float g_e2[KCB];                     // ||e_k||^2, ref rounding (mul+add, seq d)
__device__ float g_partial[GRID * PAIRS_PER_CTA];

__device__ __forceinline__ void ffma2(u64 &acc, u64 a, u64 b) {
    // packed dual-fp32 FMA; per-component identical to scalar fma.rn.f32
    asm("fma.rn.f32x2 %0, %1, %2, %0;" : "+l"(acc) : "l"(a), "l"(b));
}
__device__ __forceinline__ u64 fma2v(u64 a, u64 b, u64 c) {
    u64 d;
    asm("fma.rn.f32x2 %0, %1, %2, %3;" : "=l"(d) : "l"(a), "l"(b), "l"(c));
    return d;
}
__device__ __forceinline__ u64 add2(u64 a, u64 b) {
    u64 d;
    asm("add.rn.f32x2 %0, %1, %2;" : "=l"(d) : "l"(a), "l"(b));
    return d;
}
__device__ __forceinline__ u64 dup2(float v) {
    u64 u = (u64)__float_as_uint(v);
    return (u << 32) | u;
}
__device__ __forceinline__ float lo32(u64 v) { return __uint_as_float((unsigned)v); }
__device__ __forceinline__ float hi32(u64 v) { return __uint_as_float((unsigned)(v >> 32)); }

// ---------------------------------------------------------------------------
// Prep: transpose codebook to [K][D]; e2 with reference rounding:
//   sequential d, square rounded separately (mul), then add (XLA reduce order)
// ---------------------------------------------------------------------------
__global__ void vq_prep(const float* __restrict__ emb) {
    int t = threadIdx.x;
    if (t < KCB) {
        float s = 0.f;
        #pragma unroll
        for (int d = 0; d < DDIM; ++d) {
            float v = emb[d * KCB + t];
            s = __fadd_rn(s, __fmul_rn(v, v));
        }
        g_e2[t] = s;
    }
    for (int i = t; i < KCB * DDIM; i += blockDim.x) {
        int k = i >> 6, d = i & 63;
        g_embT[i] = emb[d * KCB + k];
    }
}

// ---------------------------------------------------------------------------
// Main: distances + argmin + gather + loss partials
//   warp-pair: warp0 handles codes [0,256), warp1 handles [256,512)
//   dist_k = fl( fl(x2 + e2_k) - 2*dot_k ), matching the reference bitwise
// ---------------------------------------------------------------------------
__global__ void __launch_bounds__(CTA_THREADS, 1)
vq_main(const float* __restrict__ x, float* __restrict__ out) {
    extern __shared__ unsigned char smem[];
    float*  s_emb = (float*)smem;                          // [64][512] f32      131072 B
    u64*    s_e2  = (u64*)(smem + 131072);                 // [256] packed pairs   2048 B
    u64*    s_xs  = (u64*)(smem + 133120);                 // [16][8][66] dup(-x) 67584 B
    float2* s_res = (float2*)(smem + 200704);              // [8 pairs][2][8]      1024 B
    float*  s_x2  = (float*)(smem + 201728);               // [16 warps][8]         512 B

    const int tid  = threadIdx.x;
    const int warp = tid >> 5, lane = tid & 31;
    const int pairInCta = warp >> 1, wip = warp & 1;
    const int gpair  = blockIdx.x * PAIRS_PER_CTA + pairInCta;
    const int npairs = gridDim.x * PAIRS_PER_CTA;
    const int barid  = pairInCta + 8;                      // named barriers 8..15

    // CTA init: codebook (d-major) + e2 pairs into smem
    for (int i = tid; i < KCB * DDIM; i += CTA_THREADS) {
        int d = i >> 9, k = i & 511;                       // i = d*512 + k
        s_emb[i] = g_embT[k * DDIM + d];
    }
    if (tid < 256) {
        ((float2*)s_e2)[tid] = ((const float2*)g_e2)[tid];
    }
    __syncthreads();

    u64*    xw    = s_xs + warp * (ROWS_PER_BATCH * XS_STRIDE);
    float*  x2w   = s_x2 + warp * ROWS_PER_BATCH;
    float2* resP  = s_res + pairInCta * 16;                // [2][8]
    const int qbase = wip * 128;                           // u64-pair index base (k = 2q)
    const u64 two2 = dup2(2.0f);

    float lloss = 0.f;

    for (int b = gpair; b < NBATCH; b += npairs) {
        const int row0 = b * ROWS_PER_BATCH;

        // stage negated, duplicated x (8 rows = 512 contiguous floats)
        {
            const float* xb = x + (size_t)row0 * DDIM;
            #pragma unroll
            for (int t = 0; t < 16; ++t) {
                int i = lane + 32 * t;                     // flat index over 8*64
                int r = i >> 6, d = i & 63;
                xw[r * XS_STRIDE + d] = dup2(-xb[i]);
            }
        }
        __syncwarp();

        // x2 per row, Eigen predux order: 8 stride-8 partials (mul+add, seq),
        // s_j = p_j + p_{j+4}, x2 = (s0+s2) + (s1+s3)
        {
            int r = lane >> 2, c = lane & 3;
            const float2* xr = (const float2*)(xw + r * XS_STRIDE);
            float pc = 0.f, pc4 = 0.f;
            #pragma unroll
            for (int t = 0; t < 8; ++t) {
                float a = xr[8 * t + c].x;                 // -x[8t+c]
                float bb = xr[8 * t + c + 4].x;            // -x[8t+c+4]
                pc  = __fadd_rn(pc,  __fmul_rn(a, a));
                pc4 = __fadd_rn(pc4, __fmul_rn(bb, bb));
            }
            float sc = __fadd_rn(pc, pc4);
            float t0 = __fadd_rn(sc, __shfl_xor_sync(0xffffffffu, sc, 2));
            float x2 = __fadd_rn(t0, __shfl_xor_sync(0xffffffffu, t0, 1));
            if (c == 0) x2w[r] = x2;
        }
        __syncwarp();

        // accumulators = 0; acc accumulates -dot sequentially over d (fma)
        u64 acc[ROWS_PER_BATCH][4];
        #pragma unroll
        for (int r = 0; r < ROWS_PER_BATCH; ++r)
            #pragma unroll
            for (int p = 0; p < 4; ++p) acc[r][p] = 0ull;

        #pragma unroll 4
        for (int d = 0; d < DDIM; d += 2) {
            const u64* er0 = (const u64*)(s_emb + (d    ) * KCB) + qbase + lane;
            const u64* er1 = (const u64*)(s_emb + (d + 1) * KCB) + qbase + lane;
            u64 e0[4], e1[4];
            #pragma unroll
            for (int p = 0; p < 4; ++p) { e0[p] = er0[32 * p]; e1[p] = er1[32 * p]; }
            #pragma unroll
            for (int r = 0; r < ROWS_PER_BATCH; ++r) {
                ulonglong2 xv = *(const ulonglong2*)(xw + r * XS_STRIDE + d); // broadcast
                #pragma unroll
                for (int p = 0; p < 4; ++p) {
                    ffma2(acc[r][p], xv.x, e0[p]);
                    ffma2(acc[r][p], xv.y, e1[p]);
                }
            }
        }

        // per-row: dist = fl( fl(x2+e2) + 2*(-dot) ), then argmin over this half of K
        #pragma unroll
        for (int r = 0; r < ROWS_PER_BATCH; ++r) {
            u64 x2d = dup2(x2w[r]);
            float mv = 3.4e38f; int mk = 0;
            #pragma unroll
            for (int p = 0; p < 4; ++p) {
                u64 s    = add2(x2d, s_e2[qbase + lane + 32 * p]);
                u64 dist = fma2v(acc[r][p], two2, s);
                int k0 = 2 * (qbase + lane + 32 * p);
                float a = lo32(dist), c = hi32(dist);
                if (a < mv || (a == mv && k0 < mk))       { mv = a; mk = k0; }
                if (c < mv || (c == mv && (k0 + 1) < mk)) { mv = c; mk = k0 + 1; }
            }
            #pragma unroll
            for (int off = 16; off > 0; off >>= 1) {
                float ov = __shfl_down_sync(0xffffffffu, mv, off);
                int   ok = __shfl_down_sync(0xffffffffu, mk, off);
                if (ov < mv || (ov == mv && ok < mk)) { mv = ov; mk = ok; }
            }
            if (lane == 0) resP[wip * 8 + r] = make_float2(mv, __int_as_float(mk));
        }
        asm volatile("bar.sync %0, 64;" :: "r"(barid) : "memory");

        // warp0 of the pair combines halves, gathers codebook rows, writes out + loss
        if (wip == 0) {
            #pragma unroll
            for (int r = 0; r < ROWS_PER_BATCH; ++r) {
                float2 c0 = resP[r], c1 = resP[8 + r];
                int kst = (c0.x < c1.x ||
                           (c0.x == c1.x && __float_as_int(c0.y) < __float_as_int(c1.y)))
                          ? __float_as_int(c0.y) : __float_as_int(c1.y);
                const float* qrow = g_embT + (size_t)kst * DDIM;
                float q0 = qrow[lane], q1 = qrow[lane + 32];
                const float2* xf = (const float2*)(xw + r * XS_STRIDE);
                float nx0 = xf[lane].x, nx1 = xf[lane + 32].x;   // -x
                float d0 = __fadd_rn(q0, nx0);                   // fl(q - x)
                float d1 = __fadd_rn(q1, nx1);
                lloss = fmaf(d0, d0, lloss);
                lloss = fmaf(d1, d1, lloss);
                float* orow = out + (size_t)(row0 + r) * DDIM;
                orow[lane]      = __fadd_rn(-nx0, d0);           // fl(x + fl(q-x))
                orow[lane + 32] = __fadd_rn(-nx1, d1);
            }
        }
        asm volatile("bar.sync %0, 64;" :: "r"(barid) : "memory");
    }

    if (wip == 0) {
        #pragma unroll
        for (int off = 16; off > 0; off >>= 1)
            lloss += __shfl_down_sync(0xffffffffu, lloss, off);
        if (lane == 0) g_partial[gpair] = lloss;
    }
}

// ---------------------------------------------------------------------------
// Finalize: deterministic loss reduction (double accumulate)
// ---------------------------------------------------------------------------
__global__ void vq_finalize(float* __restrict__ loss_out, int npairs) {
    __shared__ double red[256];
    double s = 0.0;
    for (int i = threadIdx.x; i < npairs; i += blockDim.x) s += (double)g_partial[i];
    red[threadIdx.x] = s;
    __syncthreads();
    for (int h = 128; h > 0; h >>= 1) {
        if (threadIdx.x < h) red[threadIdx.x] += red[threadIdx.x + h];
        __syncthreads();
    }
    if (threadIdx.x == 0)
        loss_out[0] = (float)(1.25 * red[0] / (double)((long long)NROWS * DDIM));
}

// ---------------------------------------------------------------------------
extern "C" void kernel_launch(void* const* d_in, const int* in_sizes, int n_in,
                              void* d_out, int out_size) {
    const float* x   = (const float*)d_in[0];
    const float* emb = (const float*)d_in[1];
    float* out = (float*)d_out;

    const int SMEM_BYTES = 131072 + 2048 + 67584 + 1024 + 512; // 202240
    cudaFuncSetAttribute(vq_main, cudaFuncAttributeMaxDynamicSharedMemorySize, SMEM_BYTES);

    vq_prep<<<1, 512>>>(emb);
    vq_main<<<GRID, CTA_THREADS, SMEM_BYTES>>>(x, out);
    if (out_size > NROWS * DDIM)
        vq_finalize<<<1, 256>>>(out + out_size - 1, GRID * PAIRS_PER_CTA);
}

// round 4
// speedup vs baseline: 1.0011x; 1.0011x over previous
#include <cuda_runtime.h>
#include <cstdint>

#define NROWS 262144
#define DDIM 64
#define KCB 512
#define GRID 152
#define CTA_THREADS 512
#define PAIRS_PER_CTA 8           // 16 warps -> 8 warp-pairs
#define ROWS_PER_BATCH 8
#define NBATCH (NROWS / ROWS_PER_BATCH)   // 32768
#define XS_STRIDE 66              // u64 per staged row (64 + 2 pad: kills STS bank conflicts)

typedef unsigned long long u64;

// device scratch (no allocations allowed)
__device__ float g_embT[KCB * DDIM];            // codebook transposed [K][D] for gather
__device__ float g_e2[KCB];                     // ||e_k||^2, ref rounding (mul+add, seq d)
__device__ float g_partial[GRID * PAIRS_PER_CTA];

__device__ __forceinline__ void ffma2(u64 &acc, u64 a, u64 b) {
    // packed dual-fp32 FMA; per-component identical to scalar fma.rn.f32
    asm("fma.rn.f32x2 %0, %1, %2, %0;" : "+l"(acc) : "l"(a), "l"(b));
}
__device__ __forceinline__ u64 fma2v(u64 a, u64 b, u64 c) {
    u64 d;
    asm("fma.rn.f32x2 %0, %1, %2, %3;" : "=l"(d) : "l"(a), "l"(b), "l"(c));
    return d;
}
__device__ __forceinline__ u64 add2(u64 a, u64 b) {
    u64 d;
    asm("add.rn.f32x2 %0, %1, %2;" : "=l"(d) : "l"(a), "l"(b));
    return d;
}
__device__ __forceinline__ u64 dup2(float v) {
    u64 u = (u64)__float_as_uint(v);
    return (u << 32) | u;
}
__device__ __forceinline__ float lo32(u64 v) { return __uint_as_float((unsigned)v); }
__device__ __forceinline__ float hi32(u64 v) { return __uint_as_float((unsigned)(v >> 32)); }

// ---------------------------------------------------------------------------
// Prep: transpose codebook to [K][D]; e2 with reference rounding:
//   sequential d, square rounded separately (mul), then add (XLA reduce order)
// ---------------------------------------------------------------------------
__global__ void vq_prep(const float* __restrict__ emb) {
    int t = threadIdx.x;
    if (t < KCB) {
        float s = 0.f;
        #pragma unroll
        for (int d = 0; d < DDIM; ++d) {
            float v = emb[d * KCB + t];
            s = __fadd_rn(s, __fmul_rn(v, v));
        }
        g_e2[t] = s;
    }
    for (int i = t; i < KCB * DDIM; i += blockDim.x) {
        int k = i >> 6, d = i & 63;
        g_embT[i] = emb[d * KCB + k];
    }
}

// ---------------------------------------------------------------------------
// Main: distances + argmin + gather + loss partials
//   warp-pair: warp0 handles codes [0,256), warp1 handles [256,512)
//   dist_k = fl( fl(x2 + e2_k) - 2*dot_k ), matching the reference bitwise
// ---------------------------------------------------------------------------
__global__ void __launch_bounds__(CTA_THREADS, 1)
vq_main(const float* __restrict__ x, float* __restrict__ out) {
    extern __shared__ unsigned char smem[];
    float*  s_emb = (float*)smem;                          // [64][512] f32      131072 B
    u64*    s_e2  = (u64*)(smem + 131072);                 // [256] packed pairs   2048 B
    u64*    s_xs  = (u64*)(smem + 133120);                 // [16][8][66] dup(-x) 67584 B
    float2* s_res = (float2*)(smem + 200704);              // [8 pairs][2][8]      1024 B
    float*  s_x2  = (float*)(smem + 201728);               // [16 warps][8]         512 B

    const int tid  = threadIdx.x;
    const int warp = tid >> 5, lane = tid & 31;
    const int pairInCta = warp >> 1, wip = warp & 1;
    const int gpair  = blockIdx.x * PAIRS_PER_CTA + pairInCta;
    const int npairs = gridDim.x * PAIRS_PER_CTA;
    const int barid  = pairInCta + 8;                      // named barriers 8..15

    // CTA init: codebook (d-major) + e2 pairs into smem
    for (int i = tid; i < KCB * DDIM; i += CTA_THREADS) {
        int d = i >> 9, k = i & 511;                       // i = d*512 + k
        s_emb[i] = g_embT[k * DDIM + d];
    }
    if (tid < 256) {
        ((float2*)s_e2)[tid] = ((const float2*)g_e2)[tid];
    }
    __syncthreads();

    u64*    xw    = s_xs + warp * (ROWS_PER_BATCH * XS_STRIDE);
    float*  x2w   = s_x2 + warp * ROWS_PER_BATCH;
    float2* resP  = s_res + pairInCta * 16;                // [2][8]
    const int qbase = wip * 128;                           // u64-pair index base (k = 2q)
    const u64 two2 = dup2(2.0f);

    float lloss = 0.f;

    for (int b = gpair; b < NBATCH; b += npairs) {
        const int row0 = b * ROWS_PER_BATCH;

        // stage negated, duplicated x (8 rows = 512 contiguous floats)
        {
            const float* xb = x + (size_t)row0 * DDIM;
            #pragma unroll
            for (int t = 0; t < 16; ++t) {
                int i = lane + 32 * t;                     // flat index over 8*64
                int r = i >> 6, d = i & 63;
                xw[r * XS_STRIDE + d] = dup2(-xb[i]);
            }
        }
        __syncwarp();

        // x2 per row, Eigen predux order: 8 stride-8 partials (mul+add, seq),
        // s_j = p_j + p_{j+4}, x2 = (s0+s2) + (s1+s3)
        {
            int r = lane >> 2, c = lane & 3;
            const float2* xr = (const float2*)(xw + r * XS_STRIDE);
            float pc = 0.f, pc4 = 0.f;
            #pragma unroll
            for (int t = 0; t < 8; ++t) {
                float a = xr[8 * t + c].x;                 // -x[8t+c]
                float bb = xr[8 * t + c + 4].x;            // -x[8t+c+4]
                pc  = __fadd_rn(pc,  __fmul_rn(a, a));
                pc4 = __fadd_rn(pc4, __fmul_rn(bb, bb));
            }
            float sc = __fadd_rn(pc, pc4);
            float t0 = __fadd_rn(sc, __shfl_xor_sync(0xffffffffu, sc, 2));
            float x2 = __fadd_rn(t0, __shfl_xor_sync(0xffffffffu, t0, 1));
            if (c == 0) x2w[r] = x2;
        }
        __syncwarp();

        // accumulators = 0; acc accumulates -dot sequentially over d (fma)
        u64 acc[ROWS_PER_BATCH][4];
        #pragma unroll
        for (int r = 0; r < ROWS_PER_BATCH; ++r)
            #pragma unroll
            for (int p = 0; p < 4; ++p) acc[r][p] = 0ull;

        #pragma unroll 4
        for (int d = 0; d < DDIM; d += 2) {
            const u64* er0 = (const u64*)(s_emb + (d    ) * KCB) + qbase + lane;
            const u64* er1 = (const u64*)(s_emb + (d + 1) * KCB) + qbase + lane;
            u64 e0[4], e1[4];
            #pragma unroll
            for (int p = 0; p < 4; ++p) { e0[p] = er0[32 * p]; e1[p] = er1[32 * p]; }
            #pragma unroll
            for (int r = 0; r < ROWS_PER_BATCH; ++r) {
                ulonglong2 xv = *(const ulonglong2*)(xw + r * XS_STRIDE + d); // broadcast
                #pragma unroll
                for (int p = 0; p < 4; ++p) {
                    ffma2(acc[r][p], xv.x, e0[p]);
                    ffma2(acc[r][p], xv.y, e1[p]);
                }
            }
        }

        // per-row: dist = fl( fl(x2+e2) + 2*(-dot) ), then argmin over this half of K
        #pragma unroll
        for (int r = 0; r < ROWS_PER_BATCH; ++r) {
            u64 x2d = dup2(x2w[r]);
            float mv = 3.4e38f; int mk = 0;
            #pragma unroll
            for (int p = 0; p < 4; ++p) {
                u64 s    = add2(x2d, s_e2[qbase + lane + 32 * p]);
                u64 dist = fma2v(acc[r][p], two2, s);
                int k0 = 2 * (qbase + lane + 32 * p);
                float a = lo32(dist), c = hi32(dist);
                if (a < mv || (a == mv && k0 < mk))       { mv = a; mk = k0; }
                if (c < mv || (c == mv && (k0 + 1) < mk)) { mv = c; mk = k0 + 1; }
            }
            #pragma unroll
            for (int off = 16; off > 0; off >>= 1) {
                float ov = __shfl_down_sync(0xffffffffu, mv, off);
                int   ok = __shfl_down_sync(0xffffffffu, mk, off);
                if (ov < mv || (ov == mv && ok < mk)) { mv = ov; mk = ok; }
            }
            if (lane == 0) resP[wip * 8 + r] = make_float2(mv, __int_as_float(mk));
        }
        asm volatile("bar.sync %0, 64;" :: "r"(barid) : "memory");

        // warp0 of the pair combines halves, gathers codebook rows, writes out + loss
        if (wip == 0) {
            #pragma unroll
            for (int r = 0; r < ROWS_PER_BATCH; ++r) {
                float2 c0 = resP[r], c1 = resP[8 + r];
                int kst = (c0.x < c1.x ||
                           (c0.x == c1.x && __float_as_int(c0.y) < __float_as_int(c1.y)))
                          ? __float_as_int(c0.y) : __float_as_int(c1.y);
                const float* qrow = g_embT + (size_t)kst * DDIM;
                float q0 = qrow[lane], q1 = qrow[lane + 32];
                const float2* xf = (const float2*)(xw + r * XS_STRIDE);
                float nx0 = xf[lane].x, nx1 = xf[lane + 32].x;   // -x
                float d0 = __fadd_rn(q0, nx0);                   // fl(q - x)
                float d1 = __fadd_rn(q1, nx1);
                lloss = fmaf(d0, d0, lloss);
                lloss = fmaf(d1, d1, lloss);
                float* orow = out + (size_t)(row0 + r) * DDIM;
                orow[lane]      = __fadd_rn(-nx0, d0);           // fl(x + fl(q-x))
                orow[lane + 32] = __fadd_rn(-nx1, d1);
            }
        }
        asm volatile("bar.sync %0, 64;" :: "r"(barid) : "memory");
    }

    if (wip == 0) {
        #pragma unroll
        for (int off = 16; off > 0; off >>= 1)
            lloss += __shfl_down_sync(0xffffffffu, lloss, off);
        if (lane == 0) g_partial[gpair] = lloss;
    }
}

// ---------------------------------------------------------------------------
// Finalize: deterministic loss reduction (double accumulate)
// ---------------------------------------------------------------------------
__global__ void vq_finalize(float* __restrict__ loss_out, int npairs) {
    __shared__ double red[256];
    double s = 0.0;
    for (int i = threadIdx.x; i < npairs; i += blockDim.x) s += (double)g_partial[i];
    red[threadIdx.x] = s;
    __syncthreads();
    for (int h = 128; h > 0; h >>= 1) {
        if (threadIdx.x < h) red[threadIdx.x] += red[threadIdx.x + h];
        __syncthreads();
    }
    if (threadIdx.x == 0)
        loss_out[0] = (float)(1.25 * red[0] / (double)((long long)NROWS * DDIM));
}

// ---------------------------------------------------------------------------
extern "C" void kernel_launch(void* const* d_in, const int* in_sizes, int n_in,
                              void* d_out, int out_size) {
    const float* x   = (const float*)d_in[0];
    const float* emb = (const float*)d_in[1];
    float* out = (float*)d_out;

    const int SMEM_BYTES = 131072 + 2048 + 67584 + 1024 + 512; // 202240
    cudaFuncSetAttribute(vq_main, cudaFuncAttributeMaxDynamicSharedMemorySize, SMEM_BYTES);

    vq_prep<<<1, 512>>>(emb);
    vq_main<<<GRID, CTA_THREADS, SMEM_BYTES>>>(x, out);
    if (out_size > NROWS * DDIM)
        vq_finalize<<<1, 256>>>(out + out_size - 1, GRID * PAIRS_PER_CTA);
}